// round 1
// baseline (speedup 1.0000x reference)
#include <cuda_runtime.h>
#include <cstdint>
#include <cstddef>

// Problem dims (fixed by the dataset)
#define T_TOK 16384   // N*P = 4*4096 tokens
#define D_DIM 1024
#define H_DIM 4096
#define E_NUM 8
#define LN_EPS 1e-5f

// ---------------------------------------------------------------------------
// Scratch (device globals; no allocations allowed)
// ---------------------------------------------------------------------------
__device__ float g_xln[(size_t)T_TOK * D_DIM];            // 64 MB  LayerNormed x
__device__ float g_acc0[(size_t)T_TOK * H_DIM];           // 256 MB expert slot 0
__device__ float g_acc1[(size_t)T_TOK * H_DIM];           // 256 MB expert slot 1
__device__ int            g_list[E_NUM][T_TOK];           // per-expert token lists
__device__ unsigned char  g_slot[E_NUM][T_TOK];           // which slot (0/1) per entry
__device__ int            g_count[E_NUM];

__global__ void zero_counts_kernel() {
    if (threadIdx.x < E_NUM) g_count[threadIdx.x] = 0;
}

// ---------------------------------------------------------------------------
// Kernel 1: LayerNorm + gating + top-2 routing.  One block (256 thr) per token.
// ---------------------------------------------------------------------------
__global__ __launch_bounds__(256) void ln_gate_kernel(
    const float* __restrict__ x, const float* __restrict__ gamma,
    const float* __restrict__ beta, const float* __restrict__ Wg,
    const float* __restrict__ bg)
{
    const int t    = blockIdx.x;
    const int tid  = threadIdx.x;
    const int lane = tid & 31;
    const int warp = tid >> 5;

    __shared__ float s_x[D_DIM];
    __shared__ float s_red[16];
    __shared__ float s_stat[2];
    __shared__ float s_logit[E_NUM];

    const float4* xt = (const float4*)(x + (size_t)t * D_DIM);
    float4 v = xt[tid];                       // 256 threads * 4 = 1024 elems
    float s = v.x + v.y + v.z + v.w;
    float q = v.x * v.x + v.y * v.y + v.z * v.z + v.w * v.w;
    #pragma unroll
    for (int o = 16; o > 0; o >>= 1) {
        s += __shfl_xor_sync(0xffffffffu, s, o);
        q += __shfl_xor_sync(0xffffffffu, q, o);
    }
    if (lane == 0) { s_red[warp] = s; s_red[8 + warp] = q; }
    __syncthreads();
    if (tid == 0) {
        float ss = 0.f, qq = 0.f;
        #pragma unroll
        for (int w = 0; w < 8; ++w) { ss += s_red[w]; qq += s_red[8 + w]; }
        float mu  = ss * (1.0f / D_DIM);
        float var = qq * (1.0f / D_DIM) - mu * mu;
        s_stat[0] = mu;
        s_stat[1] = rsqrtf(var + LN_EPS);
    }
    __syncthreads();
    const float mu = s_stat[0], rs = s_stat[1];
    float4 g = ((const float4*)gamma)[tid];
    float4 b = ((const float4*)beta)[tid];
    v.x = (v.x - mu) * rs * g.x + b.x;
    v.y = (v.y - mu) * rs * g.y + b.y;
    v.z = (v.z - mu) * rs * g.z + b.z;
    v.w = (v.w - mu) * rs * g.w + b.w;
    ((float4*)s_x)[tid] = v;
    ((float4*)(g_xln + (size_t)t * D_DIM))[tid] = v;
    __syncthreads();

    // gating: warp w computes logit for expert w (softmax is monotone; the
    // gate probs are never used as weights, so top-2 of logits suffices)
    {
        const float4* wg = (const float4*)(Wg + (size_t)warp * D_DIM);
        const float4* sx = (const float4*)s_x;
        float p = 0.f;
        #pragma unroll 4
        for (int i = lane; i < D_DIM / 4; i += 32) {
            float4 a = sx[i];
            float4 w4 = wg[i];
            p += a.x * w4.x + a.y * w4.y + a.z * w4.z + a.w * w4.w;
        }
        #pragma unroll
        for (int o = 16; o > 0; o >>= 1) p += __shfl_xor_sync(0xffffffffu, p, o);
        if (lane == 0) s_logit[warp] = p + bg[warp];
    }
    __syncthreads();

    if (tid == 0) {
        float best = -1e30f, sec = -1e30f;
        int bi = 0, si = 0;
        #pragma unroll
        for (int e = 0; e < E_NUM; ++e) {
            float l = s_logit[e];
            if (l > best) { sec = best; si = bi; best = l; bi = e; }
            else if (l > sec) { sec = l; si = e; }
        }
        int p0 = atomicAdd(&g_count[bi], 1);
        g_list[bi][p0] = t; g_slot[bi][p0] = 0;
        int p1 = atomicAdd(&g_count[si], 1);
        g_list[si][p1] = t; g_slot[si][p1] = 1;
    }
}

// ---------------------------------------------------------------------------
// TF32 warp-MMA helpers
// ---------------------------------------------------------------------------
__device__ __forceinline__ uint32_t f2tf(float x) {
    uint32_t r;
    asm("cvt.rna.tf32.f32 %0, %1;" : "=r"(r) : "f"(x));
    return r;
}

__device__ __forceinline__ void mma8(float d[4], const uint32_t a[4],
                                     const uint32_t b[2]) {
    asm volatile(
        "mma.sync.aligned.m16n8k8.row.col.f32.tf32.tf32.f32 "
        "{%0,%1,%2,%3}, {%4,%5,%6,%7}, {%8,%9}, {%0,%1,%2,%3};"
        : "+f"(d[0]), "+f"(d[1]), "+f"(d[2]), "+f"(d[3])
        : "r"(a[0]), "r"(a[1]), "r"(a[2]), "r"(a[3]), "r"(b[0]), "r"(b[1]));
}

#define BM 128
#define BN 128
#define BK 16
#define SSTR 20   // padded smem row stride (floats): conflict-free frag reads

// ---------------------------------------------------------------------------
// Kernel 2: grouped expert GEMM.  out_slot[token] = xln[token] @ We[e]^T + be[e]
// grid: (T/BM, H/BN, E).  Tiles beyond count[e] exit.
// ---------------------------------------------------------------------------
__global__ __launch_bounds__(256, 1) void expert_gemm_kernel(
    const float* __restrict__ We, const float* __restrict__ be)
{
    const int e   = blockIdx.z;
    const int cnt = g_count[e];
    const int m0  = blockIdx.x * BM;
    if (m0 >= cnt) return;
    const int n0  = blockIdx.y * BN;

    __shared__ uint32_t As[2][BM * SSTR];
    __shared__ uint32_t Bs[2][BN * SSTR];

    const int tid  = threadIdx.x;
    const int lane = tid & 31;
    const int warp = tid >> 5;
    const int wm   = warp >> 1;   // 0..3
    const int wn   = warp & 1;    // 0..1

    // global-load coordinates: 2 rows per thread, 4 consecutive k (float4)
    const int r0 = tid >> 2;          // 0..63
    const int r1 = r0 + 64;           // 64..127
    const int c4 = (tid & 3) * 4;     // k offset within BK

    // Gathered A rows. Out-of-range rows just read row 0 (garbage results for
    // those rows are never written in the epilogue).
    const int tokA0 = (m0 + r0 < cnt) ? g_list[e][m0 + r0] : 0;
    const int tokA1 = (m0 + r1 < cnt) ? g_list[e][m0 + r1] : 0;
    const float* Arow0 = g_xln + (size_t)tokA0 * D_DIM;
    const float* Arow1 = g_xln + (size_t)tokA1 * D_DIM;
    const float* Brow0 = We + ((size_t)e * H_DIM + n0 + r0) * D_DIM;
    const float* Brow1 = We + ((size_t)e * H_DIM + n0 + r1) * D_DIM;

    float acc[2][8][4];
    #pragma unroll
    for (int i = 0; i < 2; ++i)
        #pragma unroll
        for (int j = 0; j < 8; ++j)
            #pragma unroll
            for (int k = 0; k < 4; ++k) acc[i][j][k] = 0.f;

    float4 ra0, ra1, rb0, rb1;
    // prologue: tile 0
    ra0 = *(const float4*)(Arow0 + c4);
    ra1 = *(const float4*)(Arow1 + c4);
    rb0 = *(const float4*)(Brow0 + c4);
    rb1 = *(const float4*)(Brow1 + c4);
    {
        uint32_t* A = &As[0][r0 * SSTR + c4];
        A[0] = f2tf(ra0.x); A[1] = f2tf(ra0.y); A[2] = f2tf(ra0.z); A[3] = f2tf(ra0.w);
        uint32_t* A2 = &As[0][r1 * SSTR + c4];
        A2[0] = f2tf(ra1.x); A2[1] = f2tf(ra1.y); A2[2] = f2tf(ra1.z); A2[3] = f2tf(ra1.w);
        uint32_t* B = &Bs[0][r0 * SSTR + c4];
        B[0] = f2tf(rb0.x); B[1] = f2tf(rb0.y); B[2] = f2tf(rb0.z); B[3] = f2tf(rb0.w);
        uint32_t* B2 = &Bs[0][r1 * SSTR + c4];
        B2[0] = f2tf(rb1.x); B2[1] = f2tf(rb1.y); B2[2] = f2tf(rb1.z); B2[3] = f2tf(rb1.w);
    }
    __syncthreads();

    const int NK = D_DIM / BK;  // 64
    int buf = 0;
    for (int it = 0; it < NK; ++it) {
        if (it + 1 < NK) {
            const int k0 = (it + 1) * BK;
            ra0 = *(const float4*)(Arow0 + k0 + c4);
            ra1 = *(const float4*)(Arow1 + k0 + c4);
            rb0 = *(const float4*)(Brow0 + k0 + c4);
            rb1 = *(const float4*)(Brow1 + k0 + c4);
        }
        #pragma unroll
        for (int ks = 0; ks < 2; ++ks) {
            const int kk = ks * 8;
            uint32_t af[2][4];
            #pragma unroll
            for (int mt = 0; mt < 2; ++mt) {
                const int rr = wm * 32 + mt * 16 + (lane >> 2);
                af[mt][0] = As[buf][rr * SSTR + kk + (lane & 3)];
                af[mt][1] = As[buf][(rr + 8) * SSTR + kk + (lane & 3)];
                af[mt][2] = As[buf][rr * SSTR + kk + 4 + (lane & 3)];
                af[mt][3] = As[buf][(rr + 8) * SSTR + kk + 4 + (lane & 3)];
            }
            #pragma unroll
            for (int nt = 0; nt < 8; ++nt) {
                const int nn = wn * 64 + nt * 8 + (lane >> 2);
                uint32_t bf[2];
                bf[0] = Bs[buf][nn * SSTR + kk + (lane & 3)];
                bf[1] = Bs[buf][nn * SSTR + kk + 4 + (lane & 3)];
                mma8(acc[0][nt], af[0], bf);
                mma8(acc[1][nt], af[1], bf);
            }
        }
        if (it + 1 < NK) {
            const int nb = buf ^ 1;
            uint32_t* A = &As[nb][r0 * SSTR + c4];
            A[0] = f2tf(ra0.x); A[1] = f2tf(ra0.y); A[2] = f2tf(ra0.z); A[3] = f2tf(ra0.w);
            uint32_t* A2 = &As[nb][r1 * SSTR + c4];
            A2[0] = f2tf(ra1.x); A2[1] = f2tf(ra1.y); A2[2] = f2tf(ra1.z); A2[3] = f2tf(ra1.w);
            uint32_t* B = &Bs[nb][r0 * SSTR + c4];
            B[0] = f2tf(rb0.x); B[1] = f2tf(rb0.y); B[2] = f2tf(rb0.z); B[3] = f2tf(rb0.w);
            uint32_t* B2 = &Bs[nb][r1 * SSTR + c4];
            B2[0] = f2tf(rb1.x); B2[1] = f2tf(rb1.y); B2[2] = f2tf(rb1.z); B2[3] = f2tf(rb1.w);
        }
        __syncthreads();
        buf ^= 1;
    }

    // epilogue: scatter (+bias) into slot buffer; two fp32 per store
    #pragma unroll
    for (int mt = 0; mt < 2; ++mt) {
        #pragma unroll
        for (int h = 0; h < 2; ++h) {
            const int m = m0 + wm * 32 + mt * 16 + (lane >> 2) + h * 8;
            if (m < cnt) {
                const int tok = g_list[e][m];
                float* dst = (g_slot[e][m] ? g_acc1 : g_acc0) + (size_t)tok * H_DIM;
                #pragma unroll
                for (int nt = 0; nt < 8; ++nt) {
                    const int col = n0 + wn * 64 + nt * 8 + 2 * (lane & 3);
                    float2 bv = *(const float2*)(be + (size_t)e * H_DIM + col);
                    float2 o;
                    o.x = acc[mt][nt][2 * h]     + bv.x;
                    o.y = acc[mt][nt][2 * h + 1] + bv.y;
                    *(float2*)(dst + col) = o;
                }
            }
        }
    }
}

// ---------------------------------------------------------------------------
// Kernel 3: condense GEMM. y = relu((acc0+acc1)/2) @ Wc^T + bc; out = x_in + y
// grid: (T/BM, D/BN)
// ---------------------------------------------------------------------------
__global__ __launch_bounds__(256, 1) void condense_gemm_kernel(
    const float* __restrict__ Wc, const float* __restrict__ bc,
    const float* __restrict__ xin, float* __restrict__ out)
{
    const int m0 = blockIdx.x * BM;
    const int n0 = blockIdx.y * BN;

    __shared__ uint32_t As[2][BM * SSTR];
    __shared__ uint32_t Bs[2][BN * SSTR];

    const int tid  = threadIdx.x;
    const int lane = tid & 31;
    const int warp = tid >> 5;
    const int wm   = warp >> 1;
    const int wn   = warp & 1;

    const int r0 = tid >> 2;
    const int r1 = r0 + 64;
    const int c4 = (tid & 3) * 4;

    const float* A0a = g_acc0 + (size_t)(m0 + r0) * H_DIM;
    const float* A0b = g_acc1 + (size_t)(m0 + r0) * H_DIM;
    const float* A1a = g_acc0 + (size_t)(m0 + r1) * H_DIM;
    const float* A1b = g_acc1 + (size_t)(m0 + r1) * H_DIM;
    const float* Brow0 = Wc + (size_t)(n0 + r0) * H_DIM;
    const float* Brow1 = Wc + (size_t)(n0 + r1) * H_DIM;

    float acc[2][8][4];
    #pragma unroll
    for (int i = 0; i < 2; ++i)
        #pragma unroll
        for (int j = 0; j < 8; ++j)
            #pragma unroll
            for (int k = 0; k < 4; ++k) acc[i][j][k] = 0.f;

    float4 ra0, ra1, rb0, rb1;

    // fused A: relu((acc0 + acc1) * 0.5)
    {
        float4 u, w;
        u = *(const float4*)(A0a + c4); w = *(const float4*)(A0b + c4);
        ra0.x = fmaxf((u.x + w.x) * 0.5f, 0.f); ra0.y = fmaxf((u.y + w.y) * 0.5f, 0.f);
        ra0.z = fmaxf((u.z + w.z) * 0.5f, 0.f); ra0.w = fmaxf((u.w + w.w) * 0.5f, 0.f);
        u = *(const float4*)(A1a + c4); w = *(const float4*)(A1b + c4);
        ra1.x = fmaxf((u.x + w.x) * 0.5f, 0.f); ra1.y = fmaxf((u.y + w.y) * 0.5f, 0.f);
        ra1.z = fmaxf((u.z + w.z) * 0.5f, 0.f); ra1.w = fmaxf((u.w + w.w) * 0.5f, 0.f);
        rb0 = *(const float4*)(Brow0 + c4);
        rb1 = *(const float4*)(Brow1 + c4);
        uint32_t* A = &As[0][r0 * SSTR + c4];
        A[0] = f2tf(ra0.x); A[1] = f2tf(ra0.y); A[2] = f2tf(ra0.z); A[3] = f2tf(ra0.w);
        uint32_t* A2 = &As[0][r1 * SSTR + c4];
        A2[0] = f2tf(ra1.x); A2[1] = f2tf(ra1.y); A2[2] = f2tf(ra1.z); A2[3] = f2tf(ra1.w);
        uint32_t* B = &Bs[0][r0 * SSTR + c4];
        B[0] = f2tf(rb0.x); B[1] = f2tf(rb0.y); B[2] = f2tf(rb0.z); B[3] = f2tf(rb0.w);
        uint32_t* B2 = &Bs[0][r1 * SSTR + c4];
        B2[0] = f2tf(rb1.x); B2[1] = f2tf(rb1.y); B2[2] = f2tf(rb1.z); B2[3] = f2tf(rb1.w);
    }
    __syncthreads();

    const int NK = H_DIM / BK;  // 256
    int buf = 0;
    for (int it = 0; it < NK; ++it) {
        if (it + 1 < NK) {
            const int k0 = (it + 1) * BK;
            float4 u, w;
            u = *(const float4*)(A0a + k0 + c4); w = *(const float4*)(A0b + k0 + c4);
            ra0.x = fmaxf((u.x + w.x) * 0.5f, 0.f); ra0.y = fmaxf((u.y + w.y) * 0.5f, 0.f);
            ra0.z = fmaxf((u.z + w.z) * 0.5f, 0.f); ra0.w = fmaxf((u.w + w.w) * 0.5f, 0.f);
            u = *(const float4*)(A1a + k0 + c4); w = *(const float4*)(A1b + k0 + c4);
            ra1.x = fmaxf((u.x + w.x) * 0.5f, 0.f); ra1.y = fmaxf((u.y + w.y) * 0.5f, 0.f);
            ra1.z = fmaxf((u.z + w.z) * 0.5f, 0.f); ra1.w = fmaxf((u.w + w.w) * 0.5f, 0.f);
            rb0 = *(const float4*)(Brow0 + k0 + c4);
            rb1 = *(const float4*)(Brow1 + k0 + c4);
        }
        #pragma unroll
        for (int ks = 0; ks < 2; ++ks) {
            const int kk = ks * 8;
            uint32_t af[2][4];
            #pragma unroll
            for (int mt = 0; mt < 2; ++mt) {
                const int rr = wm * 32 + mt * 16 + (lane >> 2);
                af[mt][0] = As[buf][rr * SSTR + kk + (lane & 3)];
                af[mt][1] = As[buf][(rr + 8) * SSTR + kk + (lane & 3)];
                af[mt][2] = As[buf][rr * SSTR + kk + 4 + (lane & 3)];
                af[mt][3] = As[buf][(rr + 8) * SSTR + kk + 4 + (lane & 3)];
            }
            #pragma unroll
            for (int nt = 0; nt < 8; ++nt) {
                const int nn = wn * 64 + nt * 8 + (lane >> 2);
                uint32_t bf[2];
                bf[0] = Bs[buf][nn * SSTR + kk + (lane & 3)];
                bf[1] = Bs[buf][nn * SSTR + kk + 4 + (lane & 3)];
                mma8(acc[0][nt], af[0], bf);
                mma8(acc[1][nt], af[1], bf);
            }
        }
        if (it + 1 < NK) {
            const int nb = buf ^ 1;
            uint32_t* A = &As[nb][r0 * SSTR + c4];
            A[0] = f2tf(ra0.x); A[1] = f2tf(ra0.y); A[2] = f2tf(ra0.z); A[3] = f2tf(ra0.w);
            uint32_t* A2 = &As[nb][r1 * SSTR + c4];
            A2[0] = f2tf(ra1.x); A2[1] = f2tf(ra1.y); A2[2] = f2tf(ra1.z); A2[3] = f2tf(ra1.w);
            uint32_t* B = &Bs[nb][r0 * SSTR + c4];
            B[0] = f2tf(rb0.x); B[1] = f2tf(rb0.y); B[2] = f2tf(rb0.z); B[3] = f2tf(rb0.w);
            uint32_t* B2 = &Bs[nb][r1 * SSTR + c4];
            B2[0] = f2tf(rb1.x); B2[1] = f2tf(rb1.y); B2[2] = f2tf(rb1.z); B2[3] = f2tf(rb1.w);
        }
        __syncthreads();
        buf ^= 1;
    }

    // epilogue: out = x_in + y + bc
    #pragma unroll
    for (int mt = 0; mt < 2; ++mt) {
        #pragma unroll
        for (int h = 0; h < 2; ++h) {
            const int trow = m0 + wm * 32 + mt * 16 + (lane >> 2) + h * 8;
            const float* xr = xin + (size_t)trow * D_DIM;
            float* orow = out + (size_t)trow * D_DIM;
            #pragma unroll
            for (int nt = 0; nt < 8; ++nt) {
                const int col = n0 + wn * 64 + nt * 8 + 2 * (lane & 3);
                float2 xv = *(const float2*)(xr + col);
                float2 bv = *(const float2*)(bc + col);
                float2 o;
                o.x = xv.x + bv.x + acc[mt][nt][2 * h];
                o.y = xv.y + bv.y + acc[mt][nt][2 * h + 1];
                *(float2*)(orow + col) = o;
            }
        }
    }
}

// ---------------------------------------------------------------------------
// Launch
// ---------------------------------------------------------------------------
extern "C" void kernel_launch(void* const* d_in, const int* in_sizes, int n_in,
                              void* d_out, int out_size) {
    (void)in_sizes; (void)n_in; (void)out_size;
    const float* x     = (const float*)d_in[0];
    const float* gamma = (const float*)d_in[1];
    const float* beta  = (const float*)d_in[2];
    const float* Wg    = (const float*)d_in[3];
    const float* bg    = (const float*)d_in[4];
    const float* We    = (const float*)d_in[5];
    const float* be    = (const float*)d_in[6];
    const float* Wc    = (const float*)d_in[7];
    const float* bc    = (const float*)d_in[8];
    float* out = (float*)d_out;

    zero_counts_kernel<<<1, 32>>>();
    ln_gate_kernel<<<T_TOK, 256>>>(x, gamma, beta, Wg, bg);

    dim3 g1(T_TOK / BM, H_DIM / BN, E_NUM);   // (128, 32, 8)
    expert_gemm_kernel<<<g1, 256>>>(We, be);

    dim3 g2(T_TOK / BM, D_DIM / BN);          // (128, 8)
    condense_gemm_kernel<<<g2, 256>>>(Wc, bc, x, out);
}

// round 6
// speedup vs baseline: 2.9272x; 2.9272x over previous
#include <cuda_runtime.h>
#include <cuda_fp16.h>
#include <cstdint>
#include <cstddef>

#define T_TOK 16384
#define D_DIM 1024
#define H_DIM 4096
#define E_NUM 8
#define LN_EPS 1e-5f

// ---------------------------------------------------------------------------
// Scratch (device globals; allocations forbidden)
// ---------------------------------------------------------------------------
__device__ __half g_x16[(size_t)T_TOK * D_DIM];             // LN(x) fp16
__device__ __half g_We16[(size_t)E_NUM * H_DIM * D_DIM];    // experts fp16
__device__ __half g_Wc16[(size_t)D_DIM * H_DIM];            // Wc * 0.5 fp16
__device__ __half g_s0[(size_t)T_TOK * H_DIM];              // slot 0
__device__ __half g_s1[(size_t)T_TOK * H_DIM];              // slot 1
__device__ __half g_a16[(size_t)T_TOK * H_DIM];             // relu(s0+s1)
__device__ int            g_list[E_NUM][T_TOK];
__device__ unsigned char  g_slot[E_NUM][T_TOK];
__device__ int            g_count[E_NUM];

__global__ void zero_counts_kernel() {
    if (threadIdx.x < E_NUM) g_count[threadIdx.x] = 0;
}

// ---------------------------------------------------------------------------
// PTX helpers (sm_80-era features only; compiles under plain sm_100)
// ---------------------------------------------------------------------------
__device__ __forceinline__ uint32_t smem_u32(const void* p) {
    uint32_t a;
    asm("{ .reg .u64 t; cvta.to.shared.u64 t, %1; cvt.u32.u64 %0, t; }"
        : "=r"(a) : "l"(p));
    return a;
}
__device__ __forceinline__ void cp_async16(uint32_t dst, const void* src) {
    asm volatile("cp.async.cg.shared.global [%0], [%1], 16;"
                 :: "r"(dst), "l"(src));
}
#define CP_COMMIT() asm volatile("cp.async.commit_group;")
#define CP_WAIT0()  asm volatile("cp.async.wait_group 0;")
#define CP_WAIT1()  asm volatile("cp.async.wait_group 1;")
#define CP_WAIT2()  asm volatile("cp.async.wait_group 2;")

#define LDSM4(r0, r1, r2, r3, addr) \
    asm volatile("ldmatrix.sync.aligned.m8n8.x4.shared.b16 {%0,%1,%2,%3}, [%4];" \
                 : "=r"(r0), "=r"(r1), "=r"(r2), "=r"(r3) : "r"(addr))

#define MMA16(d, a, b0, b1) \
    asm volatile("mma.sync.aligned.m16n8k16.row.col.f32.f16.f16.f32 " \
                 "{%0,%1,%2,%3}, {%4,%5,%6,%7}, {%8,%9}, {%0,%1,%2,%3};" \
                 : "+f"((d)[0]), "+f"((d)[1]), "+f"((d)[2]), "+f"((d)[3]) \
                 : "r"((a)[0]), "r"((a)[1]), "r"((a)[2]), "r"((a)[3]), \
                   "r"(b0), "r"(b1))

// ---------------------------------------------------------------------------
// fp32 -> fp16 weight conversion (0.5/top_k folded exactly into Wc)
// ---------------------------------------------------------------------------
__global__ void conv_We_kernel(const float* __restrict__ src) {
    size_t i = (size_t)blockIdx.x * blockDim.x + threadIdx.x;
    float4 v = ((const float4*)src)[i];
    __half2 a = __floats2half2_rn(v.x, v.y);
    __half2 b = __floats2half2_rn(v.z, v.w);
    uint2 u; u.x = *(uint32_t*)&a; u.y = *(uint32_t*)&b;
    ((uint2*)g_We16)[i] = u;
}
__global__ void conv_Wc_kernel(const float* __restrict__ src) {
    size_t i = (size_t)blockIdx.x * blockDim.x + threadIdx.x;
    float4 v = ((const float4*)src)[i];
    __half2 a = __floats2half2_rn(v.x * 0.5f, v.y * 0.5f);
    __half2 b = __floats2half2_rn(v.z * 0.5f, v.w * 0.5f);
    uint2 u; u.x = *(uint32_t*)&a; u.y = *(uint32_t*)&b;
    ((uint2*)g_Wc16)[i] = u;
}

// ---------------------------------------------------------------------------
// combine: g_a16 = relu(s0 + s1)   (the *0.5 lives in Wc)
// ---------------------------------------------------------------------------
__device__ __forceinline__ uint32_t relu_add2(uint32_t a, uint32_t b) {
    __half2 z = __float2half2_rn(0.f);
    __half2 r = __hmax2(__hadd2(*(__half2*)&a, *(__half2*)&b), z);
    return *(uint32_t*)&r;
}
__global__ void combine_kernel() {
    size_t i = (size_t)blockIdx.x * blockDim.x + threadIdx.x;
    uint4 a = ((const uint4*)g_s0)[i];
    uint4 b = ((const uint4*)g_s1)[i];
    uint4 r;
    r.x = relu_add2(a.x, b.x); r.y = relu_add2(a.y, b.y);
    r.z = relu_add2(a.z, b.z); r.w = relu_add2(a.w, b.w);
    ((uint4*)g_a16)[i] = r;
}

// ---------------------------------------------------------------------------
// Kernel 1: LayerNorm + gating + top-2 routing. One block (256 thr) per token.
// ---------------------------------------------------------------------------
__global__ __launch_bounds__(256) void ln_gate_kernel(
    const float* __restrict__ x, const float* __restrict__ gamma,
    const float* __restrict__ beta, const float* __restrict__ Wg,
    const float* __restrict__ bg)
{
    const int t    = blockIdx.x;
    const int tid  = threadIdx.x;
    const int lane = tid & 31;
    const int warp = tid >> 5;

    __shared__ float s_x[D_DIM];
    __shared__ float s_red[16];
    __shared__ float s_stat[2];
    __shared__ float s_logit[E_NUM];

    const float4* xt = (const float4*)(x + (size_t)t * D_DIM);
    float4 v = xt[tid];
    float s = v.x + v.y + v.z + v.w;
    float q = v.x * v.x + v.y * v.y + v.z * v.z + v.w * v.w;
    #pragma unroll
    for (int o = 16; o > 0; o >>= 1) {
        s += __shfl_xor_sync(0xffffffffu, s, o);
        q += __shfl_xor_sync(0xffffffffu, q, o);
    }
    if (lane == 0) { s_red[warp] = s; s_red[8 + warp] = q; }
    __syncthreads();
    if (tid == 0) {
        float ss = 0.f, qq = 0.f;
        #pragma unroll
        for (int w = 0; w < 8; ++w) { ss += s_red[w]; qq += s_red[8 + w]; }
        float mu  = ss * (1.0f / D_DIM);
        float var = qq * (1.0f / D_DIM) - mu * mu;
        s_stat[0] = mu;
        s_stat[1] = rsqrtf(var + LN_EPS);
    }
    __syncthreads();
    const float mu = s_stat[0], rs = s_stat[1];
    float4 g = ((const float4*)gamma)[tid];
    float4 b = ((const float4*)beta)[tid];
    v.x = (v.x - mu) * rs * g.x + b.x;
    v.y = (v.y - mu) * rs * g.y + b.y;
    v.z = (v.z - mu) * rs * g.z + b.z;
    v.w = (v.w - mu) * rs * g.w + b.w;
    ((float4*)s_x)[tid] = v;
    {
        __half2 h01 = __floats2half2_rn(v.x, v.y);
        __half2 h23 = __floats2half2_rn(v.z, v.w);
        uint2 u; u.x = *(uint32_t*)&h01; u.y = *(uint32_t*)&h23;
        ((uint2*)(g_x16 + (size_t)t * D_DIM))[tid] = u;
    }
    __syncthreads();

    // gating: warp w computes logit for expert w (softmax monotone, probs unused)
    {
        const float4* wg = (const float4*)(Wg + (size_t)warp * D_DIM);
        const float4* sx = (const float4*)s_x;
        float p = 0.f;
        #pragma unroll 4
        for (int i = lane; i < D_DIM / 4; i += 32) {
            float4 a = sx[i];
            float4 w4 = wg[i];
            p += a.x * w4.x + a.y * w4.y + a.z * w4.z + a.w * w4.w;
        }
        #pragma unroll
        for (int o = 16; o > 0; o >>= 1) p += __shfl_xor_sync(0xffffffffu, p, o);
        if (lane == 0) s_logit[warp] = p + bg[warp];
    }
    __syncthreads();

    if (tid == 0) {
        float best = -1e30f, sec = -1e30f;
        int bi = 0, si = 0;
        #pragma unroll
        for (int e = 0; e < E_NUM; ++e) {
            float l = s_logit[e];
            if (l > best) { sec = best; si = bi; best = l; bi = e; }
            else if (l > sec) { sec = l; si = e; }
        }
        int p0 = atomicAdd(&g_count[bi], 1);
        g_list[bi][p0] = t; g_slot[bi][p0] = 0;
        int p1 = atomicAdd(&g_count[si], 1);
        g_list[si][p1] = t; g_slot[si][p1] = 1;
    }
}

// ---------------------------------------------------------------------------
// GEMM geometry: BM=128, BN=128, BK=32 halves (64B rows, 2-bit swizzle).
// 3-stage cp.async pipeline; stage = 8KB A + 8KB B; 3*16KB = 48KB STATIC smem.
// 8 warps: wm = wid>>1 (4 x m32), wn = wid&1 (2 x n64).
// No dynamic smem, no cudaFuncSetAttribute (launch path = kernel launches only).
// ---------------------------------------------------------------------------

// one pipeline stage of compute: K=32 = 2 x k16
#define GEMM_STAGE_COMPUTE(sAb, sBb)                                          \
    _Pragma("unroll")                                                         \
    for (int ks = 0; ks < 2; ++ks) {                                          \
        uint32_t a0[4], a1[4];                                                \
        const uint32_t ca = ((((uint32_t)ks << 1) + hiA) ^ x3) << 4;          \
        LDSM4(a0[0], a0[1], a0[2], a0[3], (sAb) + aoff0 + ca);                \
        LDSM4(a1[0], a1[1], a1[2], a1[3], (sAb) + aoff0 + 1024 + ca);         \
        const uint32_t cb = ((((uint32_t)ks << 1) + hiB) ^ x3) << 4;          \
        _Pragma("unroll")                                                     \
        for (int np = 0; np < 4; ++np) {                                      \
            uint32_t bf[4];                                                   \
            LDSM4(bf[0], bf[1], bf[2], bf[3], (sBb) + boff + np * 1024 + cb); \
            MMA16(acc[0][np * 2],     a0, bf[0], bf[1]);                      \
            MMA16(acc[0][np * 2 + 1], a0, bf[2], bf[3]);                      \
            MMA16(acc[1][np * 2],     a1, bf[0], bf[1]);                      \
            MMA16(acc[1][np * 2 + 1], a1, bf[2], bf[3]);                      \
        }                                                                     \
    }

// ---------------------------------------------------------------------------
// Kernel 2: grouped expert GEMM. grid (H/128, T/128, E); tiles past count exit.
// ---------------------------------------------------------------------------
__global__ __launch_bounds__(256, 2) void expert_mm_kernel(const float* __restrict__ be)
{
    const int e   = blockIdx.z;
    const int cnt = g_count[e];
    const int m0  = blockIdx.y * 128;
    if (m0 >= cnt) return;
    const int n0  = blockIdx.x * 128;

    __shared__ __align__(1024) char smem[49152];
    const uint32_t sb = smem_u32(smem);
    // stage s: A at sb + s*16384, B at sb + s*16384 + 8192

    const int tid  = threadIdx.x;
    const int wid  = tid >> 5;
    const int lane = tid & 31;

    // ---- loader: thread = (row rb / rb+64, 16B chunk q of the 64B row) ----
    const int rb = tid >> 2;          // 0..63
    const int q  = tid & 3;           // 0..3
    const uint32_t sw0 = (uint32_t)(rb * 64 + ((q ^ (rb & 3)) << 4)); // +4096 for row+64
    const int mA0 = m0 + rb, mA1 = m0 + rb + 64;
    const __half* aptr0 = g_x16 + (size_t)g_list[e][mA0 < cnt ? mA0 : 0] * D_DIM + q * 8;
    const __half* aptr1 = g_x16 + (size_t)g_list[e][mA1 < cnt ? mA1 : 0] * D_DIM + q * 8;
    const __half* bptr0 = g_We16 + ((size_t)e * H_DIM + n0 + rb) * D_DIM + q * 8;
    const __half* bptr1 = bptr0 + (size_t)64 * D_DIM;

    // ---- compute setup ----
    const int wm = wid >> 1, wn = wid & 1;
    const uint32_t x3  = lane & 3;
    const uint32_t hiA = lane >> 4;
    const uint32_t hiB = (lane >> 3) & 1;
    const uint32_t aoff0 = (uint32_t)((wm * 32 + (lane & 15)) * 64);
    const uint32_t boff  = (uint32_t)((wn * 64 + ((lane >> 4) << 3) + (lane & 7)) * 64);

    float acc[2][8][4];
    #pragma unroll
    for (int i = 0; i < 2; ++i)
        #pragma unroll
        for (int j = 0; j < 8; ++j)
            #pragma unroll
            for (int k = 0; k < 4; ++k) acc[i][j][k] = 0.f;

    const int NC = D_DIM / 32;  // 32 chunks
    // prologue: stages 0, 1
    #pragma unroll
    for (int s = 0; s < 2; ++s) {
        const uint32_t sA = sb + s * 16384, sB = sA + 8192;
        cp_async16(sA + sw0,        aptr0 + s * 32);
        cp_async16(sA + sw0 + 4096, aptr1 + s * 32);
        cp_async16(sB + sw0,        bptr0 + s * 32);
        cp_async16(sB + sw0 + 4096, bptr1 + s * 32);
        CP_COMMIT();
    }

    #pragma unroll 1
    for (int i = 0; i < NC; ++i) {
        if (i + 2 < NC) {
            const int s = (i + 2) % 3;
            const uint32_t sA = sb + s * 16384, sB = sA + 8192;
            cp_async16(sA + sw0,        aptr0 + (i + 2) * 32);
            cp_async16(sA + sw0 + 4096, aptr1 + (i + 2) * 32);
            cp_async16(sB + sw0,        bptr0 + (i + 2) * 32);
            cp_async16(sB + sw0 + 4096, bptr1 + (i + 2) * 32);
            CP_COMMIT();
            CP_WAIT2();
        } else if (i + 1 < NC) { CP_WAIT1(); } else { CP_WAIT0(); }
        __syncthreads();
        const uint32_t sAb = sb + (i % 3) * 16384, sBb = sAb + 8192;
        GEMM_STAGE_COMPUTE(sAb, sBb);
        __syncthreads();
    }

    // ---- epilogue: + bias, fp16, scatter to slot buffers ----
    const int colb = n0 + wn * 64 + 2 * (lane & 3);
    const float* bbias = be + (size_t)e * H_DIM + colb;
    float2 bv[8];
    #pragma unroll
    for (int nf = 0; nf < 8; ++nf)
        bv[nf] = *(const float2*)(bbias + nf * 8);

    #pragma unroll
    for (int mt = 0; mt < 2; ++mt) {
        #pragma unroll
        for (int h = 0; h < 2; ++h) {
            const int m = m0 + wm * 32 + mt * 16 + h * 8 + (lane >> 2);
            if (m < cnt) {
                const int tok = g_list[e][m];
                __half* dst = (g_slot[e][m] ? g_s1 : g_s0)
                              + (size_t)tok * H_DIM + colb;
                #pragma unroll
                for (int nf = 0; nf < 8; ++nf) {
                    __half2 hv = __floats2half2_rn(acc[mt][nf][2 * h]     + bv[nf].x,
                                                   acc[mt][nf][2 * h + 1] + bv[nf].y);
                    *(__half2*)(dst + nf * 8) = hv;
                }
            }
        }
    }
}

// ---------------------------------------------------------------------------
// Kernel 3: condense GEMM. out = x_in + A(g_a16) @ (0.5*Wc)^T + bc.
// grid (D/128, T/128).
// ---------------------------------------------------------------------------
__global__ __launch_bounds__(256, 2) void condense_mm_kernel(
    const float* __restrict__ bc, const float* __restrict__ xin,
    float* __restrict__ out)
{
    const int n0 = blockIdx.x * 128;
    const int m0 = blockIdx.y * 128;

    __shared__ __align__(1024) char smem[49152];
    const uint32_t sb = smem_u32(smem);

    const int tid  = threadIdx.x;
    const int wid  = tid >> 5;
    const int lane = tid & 31;

    const int rb = tid >> 2;
    const int q  = tid & 3;
    const uint32_t sw0 = (uint32_t)(rb * 64 + ((q ^ (rb & 3)) << 4));
    const __half* aptr0 = g_a16 + (size_t)(m0 + rb) * H_DIM + q * 8;
    const __half* aptr1 = aptr0 + (size_t)64 * H_DIM;
    const __half* bptr0 = g_Wc16 + (size_t)(n0 + rb) * H_DIM + q * 8;
    const __half* bptr1 = bptr0 + (size_t)64 * H_DIM;

    const int wm = wid >> 1, wn = wid & 1;
    const uint32_t x3  = lane & 3;
    const uint32_t hiA = lane >> 4;
    const uint32_t hiB = (lane >> 3) & 1;
    const uint32_t aoff0 = (uint32_t)((wm * 32 + (lane & 15)) * 64);
    const uint32_t boff  = (uint32_t)((wn * 64 + ((lane >> 4) << 3) + (lane & 7)) * 64);

    float acc[2][8][4];
    #pragma unroll
    for (int i = 0; i < 2; ++i)
        #pragma unroll
        for (int j = 0; j < 8; ++j)
            #pragma unroll
            for (int k = 0; k < 4; ++k) acc[i][j][k] = 0.f;

    const int NC = H_DIM / 32;  // 128 chunks
    #pragma unroll
    for (int s = 0; s < 2; ++s) {
        const uint32_t sA = sb + s * 16384, sB = sA + 8192;
        cp_async16(sA + sw0,        aptr0 + s * 32);
        cp_async16(sA + sw0 + 4096, aptr1 + s * 32);
        cp_async16(sB + sw0,        bptr0 + s * 32);
        cp_async16(sB + sw0 + 4096, bptr1 + s * 32);
        CP_COMMIT();
    }

    #pragma unroll 1
    for (int i = 0; i < NC; ++i) {
        if (i + 2 < NC) {
            const int s = (i + 2) % 3;
            const uint32_t sA = sb + s * 16384, sB = sA + 8192;
            cp_async16(sA + sw0,        aptr0 + (i + 2) * 32);
            cp_async16(sA + sw0 + 4096, aptr1 + (i + 2) * 32);
            cp_async16(sB + sw0,        bptr0 + (i + 2) * 32);
            cp_async16(sB + sw0 + 4096, bptr1 + (i + 2) * 32);
            CP_COMMIT();
            CP_WAIT2();
        } else if (i + 1 < NC) { CP_WAIT1(); } else { CP_WAIT0(); }
        __syncthreads();
        const uint32_t sAb = sb + (i % 3) * 16384, sBb = sAb + 8192;
        GEMM_STAGE_COMPUTE(sAb, sBb);
        __syncthreads();
    }

    // ---- epilogue: out = x_in + y + bc ----
    const int colb = n0 + wn * 64 + 2 * (lane & 3);
    float2 bv[8];
    #pragma unroll
    for (int nf = 0; nf < 8; ++nf)
        bv[nf] = *(const float2*)(bc + colb + nf * 8);

    #pragma unroll
    for (int mt = 0; mt < 2; ++mt) {
        #pragma unroll
        for (int h = 0; h < 2; ++h) {
            const int trow = m0 + wm * 32 + mt * 16 + h * 8 + (lane >> 2);
            const float* xr = xin + (size_t)trow * D_DIM + colb;
            float* orow     = out + (size_t)trow * D_DIM + colb;
            #pragma unroll
            for (int nf = 0; nf < 8; ++nf) {
                float2 xv = *(const float2*)(xr + nf * 8);
                float2 o;
                o.x = xv.x + bv[nf].x + acc[mt][nf][2 * h];
                o.y = xv.y + bv[nf].y + acc[mt][nf][2 * h + 1];
                *(float2*)(orow + nf * 8) = o;
            }
        }
    }
}

// ---------------------------------------------------------------------------
// Launch: kernel launches ONLY (no attribute calls, no dynamic smem)
// ---------------------------------------------------------------------------
extern "C" void kernel_launch(void* const* d_in, const int* in_sizes, int n_in,
                              void* d_out, int out_size) {
    (void)in_sizes; (void)n_in; (void)out_size;
    const float* x     = (const float*)d_in[0];
    const float* gamma = (const float*)d_in[1];
    const float* beta  = (const float*)d_in[2];
    const float* Wg    = (const float*)d_in[3];
    const float* bg    = (const float*)d_in[4];
    const float* We    = (const float*)d_in[5];
    const float* be    = (const float*)d_in[6];
    const float* Wc    = (const float*)d_in[7];
    const float* bc    = (const float*)d_in[8];
    float* out = (float*)d_out;

    zero_counts_kernel<<<1, 32>>>();
    conv_We_kernel<<<(E_NUM * H_DIM * D_DIM / 4) / 256, 256>>>(We);
    conv_Wc_kernel<<<(D_DIM * H_DIM / 4) / 256, 256>>>(Wc);
    ln_gate_kernel<<<T_TOK, 256>>>(x, gamma, beta, Wg, bg);

    dim3 g1(H_DIM / 128, T_TOK / 128, E_NUM);   // (32, 128, 8); most CTAs exit
    expert_mm_kernel<<<g1, 256>>>(be);

    combine_kernel<<<((size_t)T_TOK * H_DIM / 8) / 256, 256>>>();

    dim3 g2(D_DIM / 128, T_TOK / 128);          // (8, 128)
    condense_mm_kernel<<<g2, 256>>>(bc, x, out);
}

// round 7
// speedup vs baseline: 3.6762x; 1.2558x over previous
#include <cuda_runtime.h>
#include <cuda_fp16.h>
#include <cstdint>
#include <cstddef>

#define T_TOK 16384
#define D_DIM 1024
#define H_DIM 4096
#define E_NUM 8
#define LN_EPS 1e-5f

// ---------------------------------------------------------------------------
// Scratch (device globals; allocations forbidden)
// ---------------------------------------------------------------------------
__device__ __half g_x16[(size_t)T_TOK * D_DIM];             // LN(x) fp16
__device__ __half g_We16[(size_t)E_NUM * H_DIM * D_DIM];    // experts fp16
__device__ __half g_Wc16[(size_t)D_DIM * H_DIM];            // Wc * 0.5 fp16
__device__ __half g_s0[(size_t)T_TOK * H_DIM];              // slot 0
__device__ __half g_s1[(size_t)T_TOK * H_DIM];              // slot 1
__device__ __half g_a16[(size_t)T_TOK * H_DIM];             // relu(s0+s1)
__device__ int            g_list[E_NUM][T_TOK];
__device__ unsigned char  g_slot[E_NUM][T_TOK];
__device__ int            g_count[E_NUM];

__global__ void zero_counts_kernel() {
    if (threadIdx.x < E_NUM) g_count[threadIdx.x] = 0;
}

// ---------------------------------------------------------------------------
// PTX helpers (sm_80-era features only; compiles under plain sm_100)
// ---------------------------------------------------------------------------
__device__ __forceinline__ uint32_t smem_u32(const void* p) {
    uint32_t a;
    asm("{ .reg .u64 t; cvta.to.shared.u64 t, %1; cvt.u32.u64 %0, t; }"
        : "=r"(a) : "l"(p));
    return a;
}
__device__ __forceinline__ void cp_async16(uint32_t dst, const void* src) {
    asm volatile("cp.async.cg.shared.global [%0], [%1], 16;"
                 :: "r"(dst), "l"(src));
}
#define CP_COMMIT() asm volatile("cp.async.commit_group;")
#define CP_WAIT0()  asm volatile("cp.async.wait_group 0;")
#define CP_WAIT1()  asm volatile("cp.async.wait_group 1;")

#define LDSM4(r0, r1, r2, r3, addr) \
    asm volatile("ldmatrix.sync.aligned.m8n8.x4.shared.b16 {%0,%1,%2,%3}, [%4];" \
                 : "=r"(r0), "=r"(r1), "=r"(r2), "=r"(r3) : "r"(addr))

#define MMA16(d, a, b0, b1) \
    asm volatile("mma.sync.aligned.m16n8k16.row.col.f32.f16.f16.f32 " \
                 "{%0,%1,%2,%3}, {%4,%5,%6,%7}, {%8,%9}, {%0,%1,%2,%3};" \
                 : "+f"((d)[0]), "+f"((d)[1]), "+f"((d)[2]), "+f"((d)[3]) \
                 : "r"((a)[0]), "r"((a)[1]), "r"((a)[2]), "r"((a)[3]), \
                   "r"(b0), "r"(b1))

// ---------------------------------------------------------------------------
// fp32 -> fp16 weight conversion (0.5/top_k folded exactly into Wc)
// ---------------------------------------------------------------------------
__global__ void conv_We_kernel(const float* __restrict__ src) {
    size_t i = (size_t)blockIdx.x * blockDim.x + threadIdx.x;
    float4 v = ((const float4*)src)[i];
    __half2 a = __floats2half2_rn(v.x, v.y);
    __half2 b = __floats2half2_rn(v.z, v.w);
    uint2 u; u.x = *(uint32_t*)&a; u.y = *(uint32_t*)&b;
    ((uint2*)g_We16)[i] = u;
}
__global__ void conv_Wc_kernel(const float* __restrict__ src) {
    size_t i = (size_t)blockIdx.x * blockDim.x + threadIdx.x;
    float4 v = ((const float4*)src)[i];
    __half2 a = __floats2half2_rn(v.x * 0.5f, v.y * 0.5f);
    __half2 b = __floats2half2_rn(v.z * 0.5f, v.w * 0.5f);
    uint2 u; u.x = *(uint32_t*)&a; u.y = *(uint32_t*)&b;
    ((uint2*)g_Wc16)[i] = u;
}

// ---------------------------------------------------------------------------
// combine: g_a16 = relu(s0 + s1)   (the *0.5 lives in Wc)
// ---------------------------------------------------------------------------
__device__ __forceinline__ uint32_t relu_add2(uint32_t a, uint32_t b) {
    __half2 z = __float2half2_rn(0.f);
    __half2 r = __hmax2(__hadd2(*(__half2*)&a, *(__half2*)&b), z);
    return *(uint32_t*)&r;
}
__global__ void combine_kernel() {
    size_t i = (size_t)blockIdx.x * blockDim.x + threadIdx.x;
    uint4 a = ((const uint4*)g_s0)[i];
    uint4 b = ((const uint4*)g_s1)[i];
    uint4 r;
    r.x = relu_add2(a.x, b.x); r.y = relu_add2(a.y, b.y);
    r.z = relu_add2(a.z, b.z); r.w = relu_add2(a.w, b.w);
    ((uint4*)g_a16)[i] = r;
}

// ---------------------------------------------------------------------------
// Kernel 1: LayerNorm + gating + top-2 routing. One block (256 thr) per token.
// Gating is computed from REGISTERS against L1-resident Wg (no smem GEMV).
// ---------------------------------------------------------------------------
__global__ __launch_bounds__(256) void ln_gate_kernel(
    const float* __restrict__ x, const float* __restrict__ gamma,
    const float* __restrict__ beta, const float* __restrict__ Wg,
    const float* __restrict__ bg)
{
    const int t    = blockIdx.x;
    const int tid  = threadIdx.x;
    const int lane = tid & 31;
    const int warp = tid >> 5;

    __shared__ float s_red[16];
    __shared__ float s_stat[2];
    __shared__ float s_part[8][8];

    const float4* xt = (const float4*)(x + (size_t)t * D_DIM);
    float4 v = xt[tid];
    float s = v.x + v.y + v.z + v.w;
    float q = v.x * v.x + v.y * v.y + v.z * v.z + v.w * v.w;
    #pragma unroll
    for (int o = 16; o > 0; o >>= 1) {
        s += __shfl_xor_sync(0xffffffffu, s, o);
        q += __shfl_xor_sync(0xffffffffu, q, o);
    }
    if (lane == 0) { s_red[warp] = s; s_red[8 + warp] = q; }
    __syncthreads();
    if (tid == 0) {
        float ss = 0.f, qq = 0.f;
        #pragma unroll
        for (int w = 0; w < 8; ++w) { ss += s_red[w]; qq += s_red[8 + w]; }
        float mu  = ss * (1.0f / D_DIM);
        float var = qq * (1.0f / D_DIM) - mu * mu;
        s_stat[0] = mu;
        s_stat[1] = rsqrtf(var + LN_EPS);
    }
    __syncthreads();
    const float mu = s_stat[0], rs = s_stat[1];
    float4 g = ((const float4*)gamma)[tid];
    float4 b = ((const float4*)beta)[tid];
    v.x = (v.x - mu) * rs * g.x + b.x;
    v.y = (v.y - mu) * rs * g.y + b.y;
    v.z = (v.z - mu) * rs * g.z + b.z;
    v.w = (v.w - mu) * rs * g.w + b.w;
    {
        __half2 h01 = __floats2half2_rn(v.x, v.y);
        __half2 h23 = __floats2half2_rn(v.z, v.w);
        uint2 u; u.x = *(uint32_t*)&h01; u.y = *(uint32_t*)&h23;
        ((uint2*)(g_x16 + (size_t)t * D_DIM))[tid] = u;
    }

    // gating partials: each thread dots its 4 normalized values with Wg[e]
    float p[E_NUM];
    #pragma unroll
    for (int e = 0; e < E_NUM; ++e) {
        float4 w = ((const float4*)(Wg + (size_t)e * D_DIM))[tid];
        p[e] = v.x * w.x + v.y * w.y + v.z * w.z + v.w * w.w;
    }
    #pragma unroll
    for (int o = 16; o > 0; o >>= 1) {
        #pragma unroll
        for (int e = 0; e < E_NUM; ++e)
            p[e] += __shfl_xor_sync(0xffffffffu, p[e], o);
    }
    if (lane == 0) {
        #pragma unroll
        for (int e = 0; e < E_NUM; ++e) s_part[warp][e] = p[e];
    }
    __syncthreads();

    if (tid == 0) {
        float best = -1e30f, sec = -1e30f;
        int bi = 0, si = 0;
        #pragma unroll
        for (int e = 0; e < E_NUM; ++e) {
            float l = bg[e];
            #pragma unroll
            for (int w = 0; w < 8; ++w) l += s_part[w][e];
            if (l > best) { sec = best; si = bi; best = l; bi = e; }
            else if (l > sec) { sec = l; si = e; }
        }
        int p0 = atomicAdd(&g_count[bi], 1);
        g_list[bi][p0] = t; g_slot[bi][p0] = 0;
        int p1 = atomicAdd(&g_count[si], 1);
        g_list[si][p1] = t; g_slot[si][p1] = 1;
    }
}

// ---------------------------------------------------------------------------
// GEMM geometry: BM=128, BN=128, BK=32 halves. PACKED layout: logical rows
// (2r, 2r+1) share one 128B physical line; chunk = (q | (m&1)<<2) ^ ((m>>1)&7).
// An ldmatrix phase (8 consecutive rows, fixed q) touches all 8 distinct 16B
// quarters of the bank space -> conflict-free. 3-stage cp.async pipeline,
// 3 x 16KB = 48KB STATIC smem; ONE __syncthreads per K-chunk.
// ---------------------------------------------------------------------------

// one pipeline stage of compute: K=32 = 2 x k16
#define GEMM_STAGE_COMPUTE(sAb, sBb)                                           \
    _Pragma("unroll")                                                          \
    for (int ks = 0; ks < 2; ++ks) {                                           \
        uint32_t a0[4], a1[4];                                                 \
        const uint32_t qa = ((uint32_t)ks << 1) + hiA;                         \
        const uint32_t ca = ((qa | a_h) ^ a_sw) << 4;                          \
        LDSM4(a0[0], a0[1], a0[2], a0[3], (sAb) + a_phys + ca);                \
        LDSM4(a1[0], a1[1], a1[2], a1[3], (sAb) + a_phys + 1024 + ca);         \
        const uint32_t qb = ((uint32_t)ks << 1) + hiB;                         \
        const uint32_t cb = ((qb | b_h) ^ b_sw) << 4;                          \
        _Pragma("unroll")                                                      \
        for (int np = 0; np < 4; ++np) {                                       \
            uint32_t bf[4];                                                    \
            LDSM4(bf[0], bf[1], bf[2], bf[3],                                  \
                  (sBb) + b_phys + np * 1024 + cb);                            \
            MMA16(acc[0][np * 2],     a0, bf[0], bf[1]);                       \
            MMA16(acc[0][np * 2 + 1], a0, bf[2], bf[3]);                       \
            MMA16(acc[1][np * 2],     a1, bf[0], bf[1]);                       \
            MMA16(acc[1][np * 2 + 1], a1, bf[2], bf[3]);                       \
        }                                                                      \
    }

// ---------------------------------------------------------------------------
// Kernel 2: grouped expert GEMM. grid (H/128, T/128, E); tiles past count exit.
// ---------------------------------------------------------------------------
__global__ __launch_bounds__(256, 2) void expert_mm_kernel(const float* __restrict__ be)
{
    const int e   = blockIdx.z;
    const int cnt = g_count[e];
    const int m0  = blockIdx.y * 128;
    if (m0 >= cnt) return;
    const int n0  = blockIdx.x * 128;

    __shared__ __align__(1024) char smem[49152];
    const uint32_t sb = smem_u32(smem);

    const int tid  = threadIdx.x;
    const int wid  = tid >> 5;
    const int lane = tid & 31;

    // ---- loader: thread = (logical row rb / rb+64, 16B chunk q) ----
    const int rb = tid >> 2;          // 0..63
    const int q  = tid & 3;           // 0..3
    const uint32_t sw0 = (uint32_t)((rb >> 1) * 128 +
        ((((uint32_t)q | ((rb & 1) << 2)) ^ ((rb >> 1) & 7)) << 4));
    const int mA0 = m0 + rb, mA1 = m0 + rb + 64;
    const __half* aptr0 = g_x16 + (size_t)g_list[e][mA0 < cnt ? mA0 : 0] * D_DIM + q * 8;
    const __half* aptr1 = g_x16 + (size_t)g_list[e][mA1 < cnt ? mA1 : 0] * D_DIM + q * 8;
    const __half* bptr0 = g_We16 + ((size_t)e * H_DIM + n0 + rb) * D_DIM + q * 8;
    const __half* bptr1 = bptr0 + (size_t)64 * D_DIM;

    // ---- compute setup (packed addressing) ----
    const int wm = wid >> 1, wn = wid & 1;
    const uint32_t hiA = lane >> 4;
    const uint32_t hiB = (lane >> 3) & 1;
    const uint32_t mr = (uint32_t)(wm * 32 + (lane & 15));
    const uint32_t a_phys = (mr >> 1) * 128;
    const uint32_t a_h    = (mr & 1) << 2;
    const uint32_t a_sw   = (mr >> 1) & 7;
    const uint32_t nr = (uint32_t)(wn * 64 + ((lane >> 4) << 3) + (lane & 7));
    const uint32_t b_phys = (nr >> 1) * 128;
    const uint32_t b_h    = (nr & 1) << 2;
    const uint32_t b_sw   = (nr >> 1) & 7;

    float acc[2][8][4];
    #pragma unroll
    for (int i = 0; i < 2; ++i)
        #pragma unroll
        for (int j = 0; j < 8; ++j)
            #pragma unroll
            for (int k = 0; k < 4; ++k) acc[i][j][k] = 0.f;

    const int NC = D_DIM / 32;  // 32 chunks
    // prologue: stages 0, 1
    #pragma unroll
    for (int s = 0; s < 2; ++s) {
        const uint32_t sA = sb + s * 16384, sB = sA + 8192;
        cp_async16(sA + sw0,        aptr0 + s * 32);
        cp_async16(sA + sw0 + 4096, aptr1 + s * 32);
        cp_async16(sB + sw0,        bptr0 + s * 32);
        cp_async16(sB + sw0 + 4096, bptr1 + s * 32);
        CP_COMMIT();
    }

    #pragma unroll 1
    for (int i = 0; i < NC; ++i) {
        if (i + 1 < NC) { CP_WAIT1(); } else { CP_WAIT0(); }
        __syncthreads();
        if (i + 2 < NC) {
            const int s = (i + 2) % 3;
            const uint32_t sA = sb + s * 16384, sB = sA + 8192;
            cp_async16(sA + sw0,        aptr0 + (i + 2) * 32);
            cp_async16(sA + sw0 + 4096, aptr1 + (i + 2) * 32);
            cp_async16(sB + sw0,        bptr0 + (i + 2) * 32);
            cp_async16(sB + sw0 + 4096, bptr1 + (i + 2) * 32);
            CP_COMMIT();
        }
        const uint32_t sAb = sb + (i % 3) * 16384, sBb = sAb + 8192;
        GEMM_STAGE_COMPUTE(sAb, sBb);
    }

    // ---- epilogue: + bias, fp16, scatter to slot buffers ----
    const int colb = n0 + wn * 64 + 2 * (lane & 3);
    const float* bbias = be + (size_t)e * H_DIM + colb;
    float2 bv[8];
    #pragma unroll
    for (int nf = 0; nf < 8; ++nf)
        bv[nf] = *(const float2*)(bbias + nf * 8);

    #pragma unroll
    for (int mt = 0; mt < 2; ++mt) {
        #pragma unroll
        for (int h = 0; h < 2; ++h) {
            const int m = m0 + wm * 32 + mt * 16 + h * 8 + (lane >> 2);
            if (m < cnt) {
                const int tok = g_list[e][m];
                __half* dst = (g_slot[e][m] ? g_s1 : g_s0)
                              + (size_t)tok * H_DIM + colb;
                #pragma unroll
                for (int nf = 0; nf < 8; ++nf) {
                    __half2 hv = __floats2half2_rn(acc[mt][nf][2 * h]     + bv[nf].x,
                                                   acc[mt][nf][2 * h + 1] + bv[nf].y);
                    *(__half2*)(dst + nf * 8) = hv;
                }
            }
        }
    }
}

// ---------------------------------------------------------------------------
// Kernel 3: condense GEMM. out = x_in + A(g_a16) @ (0.5*Wc)^T + bc.
// grid (D/128, T/128).
// ---------------------------------------------------------------------------
__global__ __launch_bounds__(256, 2) void condense_mm_kernel(
    const float* __restrict__ bc, const float* __restrict__ xin,
    float* __restrict__ out)
{
    const int n0 = blockIdx.x * 128;
    const int m0 = blockIdx.y * 128;

    __shared__ __align__(1024) char smem[49152];
    const uint32_t sb = smem_u32(smem);

    const int tid  = threadIdx.x;
    const int wid  = tid >> 5;
    const int lane = tid & 31;

    const int rb = tid >> 2;
    const int q  = tid & 3;
    const uint32_t sw0 = (uint32_t)((rb >> 1) * 128 +
        ((((uint32_t)q | ((rb & 1) << 2)) ^ ((rb >> 1) & 7)) << 4));
    const __half* aptr0 = g_a16 + (size_t)(m0 + rb) * H_DIM + q * 8;
    const __half* aptr1 = aptr0 + (size_t)64 * H_DIM;
    const __half* bptr0 = g_Wc16 + (size_t)(n0 + rb) * H_DIM + q * 8;
    const __half* bptr1 = bptr0 + (size_t)64 * H_DIM;

    const int wm = wid >> 1, wn = wid & 1;
    const uint32_t hiA = lane >> 4;
    const uint32_t hiB = (lane >> 3) & 1;
    const uint32_t mr = (uint32_t)(wm * 32 + (lane & 15));
    const uint32_t a_phys = (mr >> 1) * 128;
    const uint32_t a_h    = (mr & 1) << 2;
    const uint32_t a_sw   = (mr >> 1) & 7;
    const uint32_t nr = (uint32_t)(wn * 64 + ((lane >> 4) << 3) + (lane & 7));
    const uint32_t b_phys = (nr >> 1) * 128;
    const uint32_t b_h    = (nr & 1) << 2;
    const uint32_t b_sw   = (nr >> 1) & 7;

    float acc[2][8][4];
    #pragma unroll
    for (int i = 0; i < 2; ++i)
        #pragma unroll
        for (int j = 0; j < 8; ++j)
            #pragma unroll
            for (int k = 0; k < 4; ++k) acc[i][j][k] = 0.f;

    const int NC = H_DIM / 32;  // 128 chunks
    #pragma unroll
    for (int s = 0; s < 2; ++s) {
        const uint32_t sA = sb + s * 16384, sB = sA + 8192;
        cp_async16(sA + sw0,        aptr0 + s * 32);
        cp_async16(sA + sw0 + 4096, aptr1 + s * 32);
        cp_async16(sB + sw0,        bptr0 + s * 32);
        cp_async16(sB + sw0 + 4096, bptr1 + s * 32);
        CP_COMMIT();
    }

    #pragma unroll 1
    for (int i = 0; i < NC; ++i) {
        if (i + 1 < NC) { CP_WAIT1(); } else { CP_WAIT0(); }
        __syncthreads();
        if (i + 2 < NC) {
            const int s = (i + 2) % 3;
            const uint32_t sA = sb + s * 16384, sB = sA + 8192;
            cp_async16(sA + sw0,        aptr0 + (i + 2) * 32);
            cp_async16(sA + sw0 + 4096, aptr1 + (i + 2) * 32);
            cp_async16(sB + sw0,        bptr0 + (i + 2) * 32);
            cp_async16(sB + sw0 + 4096, bptr1 + (i + 2) * 32);
            CP_COMMIT();
        }
        const uint32_t sAb = sb + (i % 3) * 16384, sBb = sAb + 8192;
        GEMM_STAGE_COMPUTE(sAb, sBb);
    }

    // ---- epilogue: out = x_in + y + bc ----
    const int colb = n0 + wn * 64 + 2 * (lane & 3);
    float2 bv[8];
    #pragma unroll
    for (int nf = 0; nf < 8; ++nf)
        bv[nf] = *(const float2*)(bc + colb + nf * 8);

    #pragma unroll
    for (int mt = 0; mt < 2; ++mt) {
        #pragma unroll
        for (int h = 0; h < 2; ++h) {
            const int trow = m0 + wm * 32 + mt * 16 + h * 8 + (lane >> 2);
            const float* xr = xin + (size_t)trow * D_DIM + colb;
            float* orow     = out + (size_t)trow * D_DIM + colb;
            #pragma unroll
            for (int nf = 0; nf < 8; ++nf) {
                float2 xv = *(const float2*)(xr + nf * 8);
                float2 o;
                o.x = xv.x + bv[nf].x + acc[mt][nf][2 * h];
                o.y = xv.y + bv[nf].y + acc[mt][nf][2 * h + 1];
                *(float2*)(orow + nf * 8) = o;
            }
        }
    }
}

// ---------------------------------------------------------------------------
// Launch: kernel launches ONLY (no attribute calls, no dynamic smem)
// ---------------------------------------------------------------------------
extern "C" void kernel_launch(void* const* d_in, const int* in_sizes, int n_in,
                              void* d_out, int out_size) {
    (void)in_sizes; (void)n_in; (void)out_size;
    const float* x     = (const float*)d_in[0];
    const float* gamma = (const float*)d_in[1];
    const float* beta  = (const float*)d_in[2];
    const float* Wg    = (const float*)d_in[3];
    const float* bg    = (const float*)d_in[4];
    const float* We    = (const float*)d_in[5];
    const float* be    = (const float*)d_in[6];
    const float* Wc    = (const float*)d_in[7];
    const float* bc    = (const float*)d_in[8];
    float* out = (float*)d_out;

    zero_counts_kernel<<<1, 32>>>();
    conv_We_kernel<<<(E_NUM * H_DIM * D_DIM / 4) / 256, 256>>>(We);
    conv_Wc_kernel<<<(D_DIM * H_DIM / 4) / 256, 256>>>(Wc);
    ln_gate_kernel<<<T_TOK, 256>>>(x, gamma, beta, Wg, bg);

    dim3 g1(H_DIM / 128, T_TOK / 128, E_NUM);   // (32, 128, 8); most CTAs exit
    expert_mm_kernel<<<g1, 256>>>(be);

    combine_kernel<<<((size_t)T_TOK * H_DIM / 8) / 256, 256>>>();

    dim3 g2(D_DIM / 128, T_TOK / 128);          // (8, 128)
    condense_mm_kernel<<<g2, 256>>>(bc, x, out);
}